// round 3
// baseline (speedup 1.0000x reference)
#include <cuda_runtime.h>

// ---------------- problem constants ----------------
#define B_    32
#define S_    2048
#define DIN   512
#define NCH   1024          // D_model
#define WLD   3072          // leading dim of W/V (3*D_model)
#define MTOT  (B_*S_)       // 65536 rows
#define NCHUNK 16
#define CS    (S_/NCHUNK)   // 128

// ---------------- scratch (device globals; no allocation allowed) ----------------
__device__ float2 g_fz[67108864];          // [MTOT][NCH] {f,z}  (512 MB)
__device__ float2 g_part[NCHUNK * B_ * NCH]; // chunk partials {P, c}
__device__ float  g_c[B_ * NCH];           // c at last timestep
__device__ float  g_q0[B_ * NCH];
__device__ float  g_q1[B_ * NCH];

// ---------------- f32x2 packed-FMA helpers (sm_100+ PTX) ----------------
typedef unsigned long long ull;

__device__ __forceinline__ ull pk2(float v) {
    ull r;
    asm("mov.b64 %0, {%1, %1};" : "=l"(r) : "f"(v));
    return r;
}
__device__ __forceinline__ void fma2(ull& d, ull a, ull b) {
    asm("fma.rn.f32x2 %0, %1, %2, %0;" : "+l"(d) : "l"(a), "l"(b));
}
__device__ __forceinline__ float2 up2(ull v) {
    float2 r;
    asm("mov.b64 {%0, %1}, %2;" : "=f"(r.x), "=f"(r.y) : "l"(v));
    return r;
}

__device__ __forceinline__ float sigmoidf_(float x) {
    return __fdividef(1.0f, 1.0f + __expf(-x));
}
__device__ __forceinline__ float tanhf_(float x) {
    x = fminf(fmaxf(x, -15.0f), 15.0f);
    float e = __expf(-2.0f * x);
    return __fdividef(1.0f - e, 1.0f + e);
}

// ---------------- big fused GEMM: pre_f/pre_z -> activations -> g_fz ----------------
// Tile: BM=128 rows (b*s), BN=64 channels, both f and z planes, BK=16 over K=512.
// A has two operands (x_s, x_{s-1}); B has four tiles (Wf, Vf, Wz, Vz).
#define BM 128
#define BN 64
#define BK 16

__global__ __launch_bounds__(256, 2)
void gemm_fz(const float* __restrict__ x,
             const float* __restrict__ W,
             const float* __restrict__ V,
             const float* __restrict__ Vb)
{
    __shared__ float As_x[BK][BM];
    __shared__ float As_p[BK][BM];
    __shared__ float Bs[4][BK][BN];   // 0:Wf 1:Vf 2:Wz 3:Vz

    const int t  = threadIdx.x;
    const int m0 = blockIdx.y * BM;
    const int n0 = blockIdx.x * BN;
    const int tx = t & 15;     // n-dir: 16 groups of 4 cols
    const int ty = t >> 4;     // m-dir: 16 groups of 8 rows

    ull accF[8][2], accZ[8][2];
#pragma unroll
    for (int i = 0; i < 8; i++) {
        accF[i][0] = 0ull; accF[i][1] = 0ull;
        accZ[i][0] = 0ull; accZ[i][1] = 0ull;
    }

    for (int k0 = 0; k0 < DIN; k0 += BK) {
        // ---- load A tiles (x and xprev), transposed to [k][m] ----
#pragma unroll
        for (int l = 0; l < 2; l++) {
            int idx = t + l * 256;          // 0..511
            int row = idx >> 2;             // 0..127
            int c4  = (idx & 3) * 4;        // 0,4,8,12
            int m   = m0 + row;
            float4 vx = *reinterpret_cast<const float4*>(&x[(size_t)m * DIN + k0 + c4]);
            As_x[c4 + 0][row] = vx.x;
            As_x[c4 + 1][row] = vx.y;
            As_x[c4 + 2][row] = vx.z;
            As_x[c4 + 3][row] = vx.w;
            float4 vp;
            if ((m & (S_ - 1)) == 0) {      // s == 0 -> xprev is zero
                vp = make_float4(0.f, 0.f, 0.f, 0.f);
            } else {
                vp = *reinterpret_cast<const float4*>(&x[(size_t)(m - 1) * DIN + k0 + c4]);
            }
            As_p[c4 + 0][row] = vp.x;
            As_p[c4 + 1][row] = vp.y;
            As_p[c4 + 2][row] = vp.z;
            As_p[c4 + 3][row] = vp.w;
        }
        // ---- load B tiles (Wf, Vf, Wz, Vz) ----
        {
            int kk = t >> 4;                // 0..15
            int n4 = (t & 15) * 4;          // 0..60
            const float* gW = W + (size_t)(k0 + kk) * WLD;
            const float* gV = V + (size_t)(k0 + kk) * WLD;
            *reinterpret_cast<float4*>(&Bs[0][kk][n4]) = *reinterpret_cast<const float4*>(&gW[n0 + n4]);
            *reinterpret_cast<float4*>(&Bs[1][kk][n4]) = *reinterpret_cast<const float4*>(&gV[n0 + n4]);
            *reinterpret_cast<float4*>(&Bs[2][kk][n4]) = *reinterpret_cast<const float4*>(&gW[NCH + n0 + n4]);
            *reinterpret_cast<float4*>(&Bs[3][kk][n4]) = *reinterpret_cast<const float4*>(&gV[NCH + n0 + n4]);
        }
        __syncthreads();

#pragma unroll
        for (int k = 0; k < BK; k++) {
            ull bwf0 = *reinterpret_cast<ull*>(&Bs[0][k][tx * 4]);
            ull bwf1 = *reinterpret_cast<ull*>(&Bs[0][k][tx * 4 + 2]);
            ull bvf0 = *reinterpret_cast<ull*>(&Bs[1][k][tx * 4]);
            ull bvf1 = *reinterpret_cast<ull*>(&Bs[1][k][tx * 4 + 2]);
            ull bwz0 = *reinterpret_cast<ull*>(&Bs[2][k][tx * 4]);
            ull bwz1 = *reinterpret_cast<ull*>(&Bs[2][k][tx * 4 + 2]);
            ull bvz0 = *reinterpret_cast<ull*>(&Bs[3][k][tx * 4]);
            ull bvz1 = *reinterpret_cast<ull*>(&Bs[3][k][tx * 4 + 2]);
#pragma unroll
            for (int i = 0; i < 8; i++) {
                ull pax = pk2(As_x[k][ty * 8 + i]);
                ull pap = pk2(As_p[k][ty * 8 + i]);
                fma2(accF[i][0], pax, bwf0); fma2(accF[i][0], pap, bvf0);
                fma2(accF[i][1], pax, bwf1); fma2(accF[i][1], pap, bvf1);
                fma2(accZ[i][0], pax, bwz0); fma2(accZ[i][0], pap, bvz0);
                fma2(accZ[i][1], pax, bwz1); fma2(accZ[i][1], pap, bvz1);
            }
        }
        __syncthreads();
    }

    // ---- epilogue: bias + activations, store {f,z} ----
#pragma unroll
    for (int i = 0; i < 8; i++) {
        int m = m0 + ty * 8 + i;
#pragma unroll
        for (int j2 = 0; j2 < 2; j2++) {
            int n = n0 + tx * 4 + j2 * 2;
            float2 pf = up2(accF[i][j2]);
            float2 pz = up2(accZ[i][j2]);

            float f0 = sigmoidf_(pf.x + Vb[n]);
            float z0 = (1.0f - f0) * tanhf_(pz.x + Vb[NCH + n]);
            g_fz[(size_t)m * NCH + n] = make_float2(f0, z0);

            float f1 = sigmoidf_(pf.y + Vb[n + 1]);
            float z1 = (1.0f - f1) * tanhf_(pz.y + Vb[NCH + n + 1]);
            g_fz[(size_t)m * NCH + n + 1] = make_float2(f1, z1);
        }
    }
}

// ---------------- chunked fo-pool scan ----------------
__global__ __launch_bounds__(256)
void scan_chunk()
{
    int idx   = blockIdx.x * 256 + threadIdx.x;   // 524288 total
    int k     = idx & (NCH - 1);
    int chunk = (idx >> 10) & (NCHUNK - 1);
    int b     = idx >> 14;

    size_t base = ((size_t)(b * S_ + chunk * CS)) * NCH + k;
    float P = 1.0f, c = 0.0f;
#pragma unroll 4
    for (int s = 0; s < CS; s++) {
        float2 fz = g_fz[base + (size_t)s * NCH];
        c = fmaf(fz.x, c, fz.y);
        P *= fz.x;
    }
    g_part[chunk * (B_ * NCH) + b * NCH + k] = make_float2(P, c);
}

__global__ __launch_bounds__(256)
void scan_combine()
{
    int i = blockIdx.x * 256 + threadIdx.x;       // 32768 total
    float c = 0.0f;
#pragma unroll
    for (int ch = 0; ch < NCHUNK; ch++) {
        float2 pc = g_part[ch * (B_ * NCH) + i];
        c = fmaf(pc.x, c, pc.y);
    }
    g_c[i] = c;
}

// ---------------- head: o at last timestep, q = c_last * sigmoid(o) ----------------
__global__ __launch_bounds__(128)
void q_head(const float* __restrict__ x,
            const float* __restrict__ W,
            const float* __restrict__ V,
            const float* __restrict__ Vb)
{
    __shared__ float xl[DIN];
    __shared__ float xp[DIN];
    int b = blockIdx.y;
    int t = threadIdx.x;
    const float* rl = x + (size_t)(b * S_ + S_ - 1) * DIN;
    const float* rp = x + (size_t)(b * S_ + S_ - 2) * DIN;
    for (int i = t; i < DIN; i += 128) { xl[i] = rl[i]; xp[i] = rp[i]; }
    __syncthreads();

    int n = blockIdx.x * 128 + t;
    float acc = Vb[2 * NCH + n];
#pragma unroll 4
    for (int k = 0; k < DIN; k++) {
        acc = fmaf(xl[k], W[(size_t)k * WLD + 2 * NCH + n], acc);
        acc = fmaf(xp[k], V[(size_t)k * WLD + 2 * NCH + n], acc);
    }
    float o = sigmoidf_(acc);
    g_q0[b * NCH + n] = g_c[b * NCH + n] * o;
}

// ---------------- small MLP layers ----------------
__device__ __forceinline__ void mlp_body(const float* __restrict__ in,
                                         const float* __restrict__ Wt,
                                         const float* __restrict__ bias,
                                         float* __restrict__ out,
                                         float* s_in, int Kd, int Nd, bool relu)
{
    int b = blockIdx.y;
    int t = threadIdx.x;
    for (int i = t; i < Kd; i += 128) s_in[i] = in[b * Kd + i];
    __syncthreads();
    int n = blockIdx.x * 128 + t;
    float acc = bias[n];
#pragma unroll 8
    for (int k = 0; k < Kd; k++)
        acc = fmaf(s_in[k], Wt[(size_t)k * Nd + n], acc);
    if (relu) acc = fmaxf(acc, 0.0f);
    out[b * Nd + n] = acc;
}

__global__ __launch_bounds__(128)
void mlp1(const float* __restrict__ W0, const float* __restrict__ b0)
{
    __shared__ float s_in[NCH];
    mlp_body(g_q0, W0, b0, g_q1, s_in, NCH, NCH, true);
}

__global__ __launch_bounds__(128)
void mlp2(const float* __restrict__ W1, const float* __restrict__ b1)
{
    __shared__ float s_in[NCH];
    mlp_body(g_q1, W1, b1, g_q0, s_in, NCH, NCH, true);
}

__global__ __launch_bounds__(128)
void mlp3(const float* __restrict__ W2, const float* __restrict__ b2,
          float* __restrict__ out)
{
    __shared__ float s_in[NCH];
    mlp_body(g_q0, W2, b2, out, s_in, NCH, 128, false);
}

// ---------------- launcher ----------------
extern "C" void kernel_launch(void* const* d_in, const int* in_sizes, int n_in,
                              void* d_out, int out_size)
{
    const float* x  = (const float*)d_in[0];
    const float* W  = (const float*)d_in[1];
    const float* V  = (const float*)d_in[2];
    const float* Vb = (const float*)d_in[3];
    const float* W0 = (const float*)d_in[4];
    const float* b0 = (const float*)d_in[5];
    const float* W1 = (const float*)d_in[6];
    const float* b1 = (const float*)d_in[7];
    const float* W2 = (const float*)d_in[8];
    const float* b2 = (const float*)d_in[9];
    float* out = (float*)d_out;

    // 1) big fused GEMM + activations -> g_fz   (grid: 16 n-tiles x 512 m-tiles)
    gemm_fz<<<dim3(NCH / BN, MTOT / BM), 256>>>(x, W, V, Vb);
    // 2) chunked linear-recurrence scan
    scan_chunk<<<(B_ * NCH * NCHUNK) / 256, 256>>>();
    scan_combine<<<(B_ * NCH) / 256, 256>>>();
    // 3) head o-gate at last timestep
    q_head<<<dim3(NCH / 128, B_), 128>>>(x, W, V, Vb);
    // 4) MLP
    mlp1<<<dim3(NCH / 128, B_), 128>>>(W0, b0);
    mlp2<<<dim3(NCH / 128, B_), 128>>>(W1, b1);
    mlp3<<<dim3(1, B_), 128>>>(W2, b2, out);
}

// round 4
// speedup vs baseline: 1.0011x; 1.0011x over previous
#include <cuda_runtime.h>

// ---------------- problem constants ----------------
#define B_    32
#define S_    2048
#define DIN   512
#define NCH   1024          // D_model
#define WLD   3072          // leading dim of W/V (3*D_model)
#define MTOT  (B_*S_)       // 65536 rows
#define NCHUNK 16
#define CS    (S_/NCHUNK)   // 128

// ---------------- scratch (device globals; no allocation allowed) ----------------
__device__ float2 g_fz[67108864];          // [MTOT][NCH] {f,z}  (512 MB)
__device__ float2 g_part[NCHUNK * B_ * NCH]; // chunk partials {P, c}
__device__ float  g_c[B_ * NCH];           // c at last timestep
__device__ float  g_q0[B_ * NCH];
__device__ float  g_q1[B_ * NCH];

// ---------------- f32x2 packed-FMA helpers (sm_100+ PTX) ----------------
typedef unsigned long long ull;

__device__ __forceinline__ ull pk2(float v) {
    ull r;
    asm("mov.b64 %0, {%1, %1};" : "=l"(r) : "f"(v));
    return r;
}
__device__ __forceinline__ void fma2(ull& d, ull a, ull b) {
    asm("fma.rn.f32x2 %0, %1, %2, %0;" : "+l"(d) : "l"(a), "l"(b));
}
__device__ __forceinline__ float2 up2(ull v) {
    float2 r;
    asm("mov.b64 {%0, %1}, %2;" : "=f"(r.x), "=f"(r.y) : "l"(v));
    return r;
}

__device__ __forceinline__ float sigmoidf_(float x) {
    return __fdividef(1.0f, 1.0f + __expf(-x));
}
__device__ __forceinline__ float tanhf_(float x) {
    x = fminf(fmaxf(x, -15.0f), 15.0f);
    float e = __expf(-2.0f * x);
    return __fdividef(1.0f - e, 1.0f + e);
}

// ---------------- big fused GEMM: pre_f/pre_z -> activations -> g_fz ----------------
// Tile: BM=128 rows (b*s), BN=64 channels, both f and z planes, BK=16 over K=512.
// A has two operands (x_s, x_{s-1}); B has four tiles (Wf, Vf, Wz, Vz).
#define BM 128
#define BN 64
#define BK 16

__global__ __launch_bounds__(256, 2)
void gemm_fz(const float* __restrict__ x,
             const float* __restrict__ W,
             const float* __restrict__ V,
             const float* __restrict__ Vb)
{
    __shared__ float As_x[BK][BM];
    __shared__ float As_p[BK][BM];
    __shared__ float Bs[4][BK][BN];   // 0:Wf 1:Vf 2:Wz 3:Vz

    const int t  = threadIdx.x;
    const int m0 = blockIdx.y * BM;
    const int n0 = blockIdx.x * BN;
    const int tx = t & 15;     // n-dir: 16 groups of 4 cols
    const int ty = t >> 4;     // m-dir: 16 groups of 8 rows

    ull accF[8][2], accZ[8][2];
#pragma unroll
    for (int i = 0; i < 8; i++) {
        accF[i][0] = 0ull; accF[i][1] = 0ull;
        accZ[i][0] = 0ull; accZ[i][1] = 0ull;
    }

    for (int k0 = 0; k0 < DIN; k0 += BK) {
        // ---- load A tiles (x and xprev), transposed to [k][m] ----
#pragma unroll
        for (int l = 0; l < 2; l++) {
            int idx = t + l * 256;          // 0..511
            int row = idx >> 2;             // 0..127
            int c4  = (idx & 3) * 4;        // 0,4,8,12
            int m   = m0 + row;
            float4 vx = *reinterpret_cast<const float4*>(&x[(size_t)m * DIN + k0 + c4]);
            As_x[c4 + 0][row] = vx.x;
            As_x[c4 + 1][row] = vx.y;
            As_x[c4 + 2][row] = vx.z;
            As_x[c4 + 3][row] = vx.w;
            float4 vp;
            if ((m & (S_ - 1)) == 0) {      // s == 0 -> xprev is zero
                vp = make_float4(0.f, 0.f, 0.f, 0.f);
            } else {
                vp = *reinterpret_cast<const float4*>(&x[(size_t)(m - 1) * DIN + k0 + c4]);
            }
            As_p[c4 + 0][row] = vp.x;
            As_p[c4 + 1][row] = vp.y;
            As_p[c4 + 2][row] = vp.z;
            As_p[c4 + 3][row] = vp.w;
        }
        // ---- load B tiles (Wf, Vf, Wz, Vz) ----
        {
            int kk = t >> 4;                // 0..15
            int n4 = (t & 15) * 4;          // 0..60
            const float* gW = W + (size_t)(k0 + kk) * WLD;
            const float* gV = V + (size_t)(k0 + kk) * WLD;
            *reinterpret_cast<float4*>(&Bs[0][kk][n4]) = *reinterpret_cast<const float4*>(&gW[n0 + n4]);
            *reinterpret_cast<float4*>(&Bs[1][kk][n4]) = *reinterpret_cast<const float4*>(&gV[n0 + n4]);
            *reinterpret_cast<float4*>(&Bs[2][kk][n4]) = *reinterpret_cast<const float4*>(&gW[NCH + n0 + n4]);
            *reinterpret_cast<float4*>(&Bs[3][kk][n4]) = *reinterpret_cast<const float4*>(&gV[NCH + n0 + n4]);
        }
        __syncthreads();

#pragma unroll
        for (int k = 0; k < BK; k++) {
            ull bwf0 = *reinterpret_cast<ull*>(&Bs[0][k][tx * 4]);
            ull bwf1 = *reinterpret_cast<ull*>(&Bs[0][k][tx * 4 + 2]);
            ull bvf0 = *reinterpret_cast<ull*>(&Bs[1][k][tx * 4]);
            ull bvf1 = *reinterpret_cast<ull*>(&Bs[1][k][tx * 4 + 2]);
            ull bwz0 = *reinterpret_cast<ull*>(&Bs[2][k][tx * 4]);
            ull bwz1 = *reinterpret_cast<ull*>(&Bs[2][k][tx * 4 + 2]);
            ull bvz0 = *reinterpret_cast<ull*>(&Bs[3][k][tx * 4]);
            ull bvz1 = *reinterpret_cast<ull*>(&Bs[3][k][tx * 4 + 2]);
#pragma unroll
            for (int i = 0; i < 8; i++) {
                ull pax = pk2(As_x[k][ty * 8 + i]);
                ull pap = pk2(As_p[k][ty * 8 + i]);
                fma2(accF[i][0], pax, bwf0); fma2(accF[i][0], pap, bvf0);
                fma2(accF[i][1], pax, bwf1); fma2(accF[i][1], pap, bvf1);
                fma2(accZ[i][0], pax, bwz0); fma2(accZ[i][0], pap, bvz0);
                fma2(accZ[i][1], pax, bwz1); fma2(accZ[i][1], pap, bvz1);
            }
        }
        __syncthreads();
    }

    // ---- epilogue: bias + activations, store {f,z} ----
#pragma unroll
    for (int i = 0; i < 8; i++) {
        int m = m0 + ty * 8 + i;
#pragma unroll
        for (int j2 = 0; j2 < 2; j2++) {
            int n = n0 + tx * 4 + j2 * 2;
            float2 pf = up2(accF[i][j2]);
            float2 pz = up2(accZ[i][j2]);

            float f0 = sigmoidf_(pf.x + Vb[n]);
            float z0 = (1.0f - f0) * tanhf_(pz.x + Vb[NCH + n]);
            g_fz[(size_t)m * NCH + n] = make_float2(f0, z0);

            float f1 = sigmoidf_(pf.y + Vb[n + 1]);
            float z1 = (1.0f - f1) * tanhf_(pz.y + Vb[NCH + n + 1]);
            g_fz[(size_t)m * NCH + n + 1] = make_float2(f1, z1);
        }
    }
}

// ---------------- chunked fo-pool scan ----------------
__global__ __launch_bounds__(256)
void scan_chunk()
{
    int idx   = blockIdx.x * 256 + threadIdx.x;   // 524288 total
    int k     = idx & (NCH - 1);
    int chunk = (idx >> 10) & (NCHUNK - 1);
    int b     = idx >> 14;

    size_t base = ((size_t)(b * S_ + chunk * CS)) * NCH + k;
    float P = 1.0f, c = 0.0f;
#pragma unroll 4
    for (int s = 0; s < CS; s++) {
        float2 fz = g_fz[base + (size_t)s * NCH];
        c = fmaf(fz.x, c, fz.y);
        P *= fz.x;
    }
    g_part[chunk * (B_ * NCH) + b * NCH + k] = make_float2(P, c);
}

__global__ __launch_bounds__(256)
void scan_combine()
{
    int i = blockIdx.x * 256 + threadIdx.x;       // 32768 total
    float c = 0.0f;
#pragma unroll
    for (int ch = 0; ch < NCHUNK; ch++) {
        float2 pc = g_part[ch * (B_ * NCH) + i];
        c = fmaf(pc.x, c, pc.y);
    }
    g_c[i] = c;
}

// ---------------- head: o at last timestep, q = c_last * sigmoid(o) ----------------
__global__ __launch_bounds__(128)
void q_head(const float* __restrict__ x,
            const float* __restrict__ W,
            const float* __restrict__ V,
            const float* __restrict__ Vb)
{
    __shared__ float xl[DIN];
    __shared__ float xp[DIN];
    int b = blockIdx.y;
    int t = threadIdx.x;
    const float* rl = x + (size_t)(b * S_ + S_ - 1) * DIN;
    const float* rp = x + (size_t)(b * S_ + S_ - 2) * DIN;
    for (int i = t; i < DIN; i += 128) { xl[i] = rl[i]; xp[i] = rp[i]; }
    __syncthreads();

    int n = blockIdx.x * 128 + t;
    float acc = Vb[2 * NCH + n];
#pragma unroll 4
    for (int k = 0; k < DIN; k++) {
        acc = fmaf(xl[k], W[(size_t)k * WLD + 2 * NCH + n], acc);
        acc = fmaf(xp[k], V[(size_t)k * WLD + 2 * NCH + n], acc);
    }
    float o = sigmoidf_(acc);
    g_q0[b * NCH + n] = g_c[b * NCH + n] * o;
}

// ---------------- small MLP layers ----------------
__device__ __forceinline__ void mlp_body(const float* __restrict__ in,
                                         const float* __restrict__ Wt,
                                         const float* __restrict__ bias,
                                         float* __restrict__ out,
                                         float* s_in, int Kd, int Nd, bool relu)
{
    int b = blockIdx.y;
    int t = threadIdx.x;
    for (int i = t; i < Kd; i += 128) s_in[i] = in[b * Kd + i];
    __syncthreads();
    int n = blockIdx.x * 128 + t;
    float acc = bias[n];
#pragma unroll 8
    for (int k = 0; k < Kd; k++)
        acc = fmaf(s_in[k], Wt[(size_t)k * Nd + n], acc);
    if (relu) acc = fmaxf(acc, 0.0f);
    out[b * Nd + n] = acc;
}

__global__ __launch_bounds__(128)
void mlp1(const float* __restrict__ W0, const float* __restrict__ b0)
{
    __shared__ float s_in[NCH];
    mlp_body(g_q0, W0, b0, g_q1, s_in, NCH, NCH, true);
}

__global__ __launch_bounds__(128)
void mlp2(const float* __restrict__ W1, const float* __restrict__ b1)
{
    __shared__ float s_in[NCH];
    mlp_body(g_q1, W1, b1, g_q0, s_in, NCH, NCH, true);
}

__global__ __launch_bounds__(128)
void mlp3(const float* __restrict__ W2, const float* __restrict__ b2,
          float* __restrict__ out)
{
    __shared__ float s_in[NCH];
    mlp_body(g_q0, W2, b2, out, s_in, NCH, 128, false);
}

// ---------------- launcher ----------------
extern "C" void kernel_launch(void* const* d_in, const int* in_sizes, int n_in,
                              void* d_out, int out_size)
{
    const float* x  = (const float*)d_in[0];
    const float* W  = (const float*)d_in[1];
    const float* V  = (const float*)d_in[2];
    const float* Vb = (const float*)d_in[3];
    const float* W0 = (const float*)d_in[4];
    const float* b0 = (const float*)d_in[5];
    const float* W1 = (const float*)d_in[6];
    const float* b1 = (const float*)d_in[7];
    const float* W2 = (const float*)d_in[8];
    const float* b2 = (const float*)d_in[9];
    float* out = (float*)d_out;

    // 1) big fused GEMM + activations -> g_fz   (grid: 16 n-tiles x 512 m-tiles)
    gemm_fz<<<dim3(NCH / BN, MTOT / BM), 256>>>(x, W, V, Vb);
    // 2) chunked linear-recurrence scan
    scan_chunk<<<(B_ * NCH * NCHUNK) / 256, 256>>>();
    scan_combine<<<(B_ * NCH) / 256, 256>>>();
    // 3) head o-gate at last timestep
    q_head<<<dim3(NCH / 128, B_), 128>>>(x, W, V, Vb);
    // 4) MLP
    mlp1<<<dim3(NCH / 128, B_), 128>>>(W0, b0);
    mlp2<<<dim3(NCH / 128, B_), 128>>>(W1, b1);
    mlp3<<<dim3(1, B_), 128>>>(W2, b2, out);
}

// round 6
// speedup vs baseline: 1.8824x; 1.8803x over previous
#include <cuda_runtime.h>
#include <cstdint>

// ---------------- problem constants ----------------
#define B_    32
#define S_    2048
#define DIN   512
#define NCH   1024
#define WLD   3072
#define MTOT  (B_*S_)       // 65536
#define KK    1024          // combined K = [x | xprev]
#define NCHUNK 16

// ---------------- scratch ----------------
__device__ float  g_A [(size_t)MTOT * KK];     // 256MB combined A (tf32-rounded)
__device__ float  g_Bt[2048 * KK];             // grouped/transposed f,z weights
__device__ float2 g_part[NCHUNK * B_ * NCH];
__device__ float  g_c [B_ * NCH];
__device__ float  g_q0[B_ * NCH];
__device__ float  g_q1[B_ * NCH];

// ---------------- helpers ----------------
__device__ __forceinline__ float sigmoidf_(float x) {
    return __fdividef(1.0f, 1.0f + __expf(-x));
}
__device__ __forceinline__ float tanhf_(float x) {
    x = fminf(fmaxf(x, -15.0f), 15.0f);
    float e = __expf(-2.0f * x);
    return __fdividef(1.0f - e, 1.0f + e);
}
__device__ __forceinline__ float tf32r(float x) {
    uint32_t r;
    asm("cvt.rna.tf32.f32 %0, %1;" : "=r"(r) : "f"(x));
    return __uint_as_float(r);
}
__device__ __forceinline__ uint32_t smem_u32(const void* p) {
    uint32_t a;
    asm("{ .reg .u64 t; cvta.to.shared.u64 t, %1; cvt.u32.u64 %0, t; }" : "=r"(a) : "l"(p));
    return a;
}

// ---------------- prep: combined A = [x | xprev], tf32 ----------------
__global__ __launch_bounds__(256)
void prepA(const float* __restrict__ x) {
    int m = blockIdx.x;
    int q = threadIdx.x;                       // float4 index within 1024-wide row
    float4 v;
    if (q < 128) {
        v = reinterpret_cast<const float4*>(x)[(size_t)m * 128 + q];
    } else {
        if ((m & (S_ - 1)) == 0) v = make_float4(0.f, 0.f, 0.f, 0.f);
        else v = reinterpret_cast<const float4*>(x)[(size_t)(m - 1) * 128 + (q - 128)];
    }
    v.x = tf32r(v.x); v.y = tf32r(v.y); v.z = tf32r(v.z); v.w = tf32r(v.w);
    reinterpret_cast<float4*>(g_A)[(size_t)m * 256 + q] = v;
}

// ---------------- prep: Bt[n'][k]; n' groups of 128 = 64 f + 64 z channels ----------------
// n' = g*128 + fz*64 + c   <->  original col = fz*NCH + g*64 + c ; k<512 -> W, else V
__global__ void prepB(const float* __restrict__ W, const float* __restrict__ V) {
    __shared__ float tile[32][33];
    int n0 = blockIdx.x * 32;
    int k0 = blockIdx.y * 32;
    int g  = n0 >> 7, rem = n0 & 127, fz = rem >> 6, c0 = rem & 63;
    int col0 = fz * NCH + g * 64 + c0;
    int tx = threadIdx.x, ty = threadIdx.y;   // block (32, 8)
#pragma unroll
    for (int i = 0; i < 4; i++) {
        int k = k0 + ty + i * 8;
        float v = (k < DIN) ? W[(size_t)k * WLD + col0 + tx]
                            : V[(size_t)(k - DIN) * WLD + col0 + tx];
        tile[ty + i * 8][tx] = v;             // [k_local][c_local]
    }
    __syncthreads();
#pragma unroll
    for (int i = 0; i < 4; i++) {
        int nl = ty + i * 8;
        g_Bt[(size_t)(n0 + nl) * KK + k0 + tx] = tf32r(tile[tx][nl]);
    }
}

// ---------------- main GEMM (tf32 mma.sync) + fused activation + chunk scan ----------------
// CTA tile 128(M=timesteps of one chunk) x 128(N=64 f + 64 z channels), BK=32.
// 8 warps, warp tile 64x32 (2x4 warp grid), m16n8k8 tf32.
#define BK 32
#define SW 36                       // padded smem row stride (words): bank = 4r+k, bijective
#define OFF_A0 0
#define OFF_A1 (128*SW)
#define OFF_B0 (2*128*SW)
#define OFF_B1 (3*128*SW)
#define OFF_VB (4*128*SW)           // 128 floats: 64 f-bias, 64 z-bias
#define OFF_SEG (OFF_VB + 128)      // float2[4][64]
#define SMEM_FLOATS (OFF_SEG + 512)
#define SMEM_BYTES  (SMEM_FLOATS * 4)   // 76288
#define FZ_STRIDE 132               // epilogue tile stride (reuses stage buffers)

__device__ __forceinline__ void stage_issue(uint32_t sbase, size_t m0, int n0,
                                            int t, int s, int buf) {
    int kb = s * BK;
    uint32_t ao = (buf ? OFF_A1 : OFF_A0);
    uint32_t bo = (buf ? OFF_B1 : OFF_B0);
#pragma unroll
    for (int j = 0; j < 4; j++) {
        int idx = t + j * 256;
        int r = idx >> 3, q = idx & 7;
        uint32_t da = sbase + ((ao + (uint32_t)r * SW + q * 4) << 2);
        const float* ga = &g_A[(m0 + r) * KK + kb + q * 4];
        asm volatile("cp.async.ca.shared.global [%0], [%1], 16;" :: "r"(da), "l"(ga));
        uint32_t db = sbase + ((bo + (uint32_t)r * SW + q * 4) << 2);
        const float* gb = &g_Bt[(size_t)(n0 + r) * KK + kb + q * 4];
        asm volatile("cp.async.ca.shared.global [%0], [%1], 16;" :: "r"(db), "l"(gb));
    }
    asm volatile("cp.async.commit_group;");
}

__global__ __launch_bounds__(256, 2)
void gemm_qrnn(const float* __restrict__ Vb) {
    extern __shared__ float sm[];
    const uint32_t sbase = smem_u32(sm);
    const int t = threadIdx.x, lane = t & 31, w = t >> 5;
    const int bx = blockIdx.x, by = blockIdx.y;
    const size_t m0 = (size_t)by * 128;
    const int n0 = bx * 128;

    if (t < 64)       sm[OFF_VB + t] = Vb[bx * 64 + t];
    else if (t < 128) sm[OFF_VB + t] = Vb[NCH + bx * 64 + (t - 64)];

    const int wm = (w >> 2) * 64, wn = (w & 3) * 32;
    const int rh = lane >> 2, cl = lane & 3;

    float acc[4][4][4];
#pragma unroll
    for (int mi = 0; mi < 4; mi++)
#pragma unroll
        for (int ni = 0; ni < 4; ni++)
#pragma unroll
            for (int j = 0; j < 4; j++) acc[mi][ni][j] = 0.0f;

    stage_issue(sbase, m0, n0, t, 0, 0);

    for (int s = 0; s < KK / BK; s++) {
        const int buf = s & 1;
        if (s + 1 < KK / BK) {
            stage_issue(sbase, m0, n0, t, s + 1, buf ^ 1);
            asm volatile("cp.async.wait_group 1;");
        } else {
            asm volatile("cp.async.wait_group 0;");
        }
        __syncthreads();

        const float* A  = &sm[buf ? OFF_A1 : OFF_A0];
        const float* Bm = &sm[buf ? OFF_B1 : OFF_B0];
#pragma unroll
        for (int k8 = 0; k8 < BK / 8; k8++) {
            const int kb = k8 * 8;
            uint32_t a[4][4], b[4][2];
#pragma unroll
            for (int mi = 0; mi < 4; mi++) {
                int row = wm + mi * 16 + rh;
                a[mi][0] = __float_as_uint(A[row * SW + kb + cl]);
                a[mi][1] = __float_as_uint(A[(row + 8) * SW + kb + cl]);
                a[mi][2] = __float_as_uint(A[row * SW + kb + cl + 4]);
                a[mi][3] = __float_as_uint(A[(row + 8) * SW + kb + cl + 4]);
            }
#pragma unroll
            for (int ni = 0; ni < 4; ni++) {
                int rowb = wn + ni * 8 + rh;
                b[ni][0] = __float_as_uint(Bm[rowb * SW + kb + cl]);
                b[ni][1] = __float_as_uint(Bm[rowb * SW + kb + cl + 4]);
            }
#pragma unroll
            for (int mi = 0; mi < 4; mi++)
#pragma unroll
                for (int ni = 0; ni < 4; ni++)
                    asm volatile(
                        "mma.sync.aligned.m16n8k8.row.col.f32.tf32.tf32.f32 "
                        "{%0,%1,%2,%3}, {%4,%5,%6,%7}, {%8,%9}, {%0,%1,%2,%3};"
                        : "+f"(acc[mi][ni][0]), "+f"(acc[mi][ni][1]),
                          "+f"(acc[mi][ni][2]), "+f"(acc[mi][ni][3])
                        : "r"(a[mi][0]), "r"(a[mi][1]), "r"(a[mi][2]), "r"(a[mi][3]),
                          "r"(b[ni][0]), "r"(b[ni][1]));
        }
        __syncthreads();
    }

    // ---- epilogue: raw pre -> smem tile [128 t][128 ch] (stride 132) ----
    float* fz = sm;
#pragma unroll
    for (int mi = 0; mi < 4; mi++) {
        int row = wm + mi * 16 + rh;
#pragma unroll
        for (int ni = 0; ni < 4; ni++) {
            int col = wn + ni * 8 + cl * 2;
            *reinterpret_cast<float2*>(&fz[row * FZ_STRIDE + col]) =
                make_float2(acc[mi][ni][0], acc[mi][ni][1]);
            *reinterpret_cast<float2*>(&fz[(row + 8) * FZ_STRIDE + col]) =
                make_float2(acc[mi][ni][2], acc[mi][ni][3]);
        }
    }
    __syncthreads();

    // ---- activations + 4x32-step serial segment scan ----
    {
        const int ch = t & 63, seg = t >> 6;
        const float bf = sm[OFF_VB + ch], bz = sm[OFF_VB + 64 + ch];
        float P = 1.0f, C = 0.0f;
#pragma unroll 4
        for (int i = 0; i < 32; i++) {
            int tt = seg * 32 + i;
            float pf = fz[tt * FZ_STRIDE + ch];
            float pz = fz[tt * FZ_STRIDE + 64 + ch];
            float f = sigmoidf_(pf + bf);
            float z = (1.0f - f) * tanhf_(pz + bz);
            C = fmaf(f, C, z);
            P *= f;
        }
        float2* segS = reinterpret_cast<float2*>(&sm[OFF_SEG]);
        segS[seg * 64 + ch] = make_float2(P, C);
    }
    __syncthreads();

    if (t < 64) {
        float2* segS = reinterpret_cast<float2*>(&sm[OFF_SEG]);
        float2 a0 = segS[t];
        float P = a0.x, C = a0.y;
#pragma unroll
        for (int sgi = 1; sgi < 4; sgi++) {
            float2 e = segS[sgi * 64 + t];
            C = fmaf(e.x, C, e.y);
            P *= e.x;
        }
        int b = by >> 4, chunk = by & 15;
        g_part[chunk * (B_ * NCH) + b * NCH + bx * 64 + t] = make_float2(P, C);
    }
}

// ---------------- serial combine over 16 chunks ----------------
__global__ __launch_bounds__(256)
void scan_combine() {
    int i = blockIdx.x * 256 + threadIdx.x;       // 32768
    float c = 0.0f;
#pragma unroll
    for (int ch = 0; ch < NCHUNK; ch++) {
        float2 pc = g_part[ch * (B_ * NCH) + i];
        c = fmaf(pc.x, c, pc.y);
    }
    g_c[i] = c;
}

// ---------------- head: weight-reuse GEMV; one CTA per channel, all 32 batches ----------------
__global__ __launch_bounds__(256)
void q_head(const float* __restrict__ W, const float* __restrict__ V,
            const float* __restrict__ Vb) {
    __shared__ float wcol[KK];
    int n = blockIdx.x;
    int t = threadIdx.x, lane = t & 31, wrp = t >> 5;
    for (int i = t; i < DIN; i += 256) {
        wcol[i]       = W[(size_t)i * WLD + 2 * NCH + n];
        wcol[DIN + i] = V[(size_t)i * WLD + 2 * NCH + n];
    }
    __syncthreads();
    float bias = Vb[2 * NCH + n];
#pragma unroll
    for (int bb = 0; bb < 4; bb++) {
        int b = wrp * 4 + bb;
        const float* xr = &g_A[(size_t)(b * S_ + S_ - 1) * KK];   // [x_last | x_prev]
        float acc = 0.0f;
#pragma unroll 8
        for (int kk = 0; kk < KK / 32; kk++)
            acc = fmaf(xr[kk * 32 + lane], wcol[kk * 32 + lane], acc);
#pragma unroll
        for (int d = 16; d > 0; d >>= 1)
            acc += __shfl_down_sync(0xffffffffu, acc, d);
        if (lane == 0)
            g_q0[b * NCH + n] = g_c[b * NCH + n] * sigmoidf_(acc + bias);
    }
}

// ---------------- small MLP layers ----------------
__device__ __forceinline__ void mlp_body(const float* __restrict__ in,
                                         const float* __restrict__ Wt,
                                         const float* __restrict__ bias,
                                         float* __restrict__ out,
                                         float* s_in, int Kd, int Nd, bool relu) {
    int b = blockIdx.y, t = threadIdx.x;
    for (int i = t; i < Kd; i += 128) s_in[i] = in[b * Kd + i];
    __syncthreads();
    int n = blockIdx.x * 128 + t;
    float acc = bias[n];
#pragma unroll 8
    for (int k = 0; k < Kd; k++)
        acc = fmaf(s_in[k], Wt[(size_t)k * Nd + n], acc);
    if (relu) acc = fmaxf(acc, 0.0f);
    out[b * Nd + n] = acc;
}
__global__ __launch_bounds__(128) void mlp1(const float* __restrict__ W0, const float* __restrict__ b0)
{ __shared__ float s[NCH]; mlp_body(g_q0, W0, b0, g_q1, s, NCH, NCH, true); }
__global__ __launch_bounds__(128) void mlp2(const float* __restrict__ W1, const float* __restrict__ b1)
{ __shared__ float s[NCH]; mlp_body(g_q1, W1, b1, g_q0, s, NCH, NCH, true); }
__global__ __launch_bounds__(128) void mlp3(const float* __restrict__ W2, const float* __restrict__ b2,
                                            float* __restrict__ out)
{ __shared__ float s[NCH]; mlp_body(g_q0, W2, b2, out, s, NCH, 128, false); }

// ---------------- launcher ----------------
extern "C" void kernel_launch(void* const* d_in, const int* in_sizes, int n_in,
                              void* d_out, int out_size) {
    const float* x  = (const float*)d_in[0];
    const float* W  = (const float*)d_in[1];
    const float* V  = (const float*)d_in[2];
    const float* Vb = (const float*)d_in[3];
    const float* W0 = (const float*)d_in[4];
    const float* b0 = (const float*)d_in[5];
    const float* W1 = (const float*)d_in[6];
    const float* b1 = (const float*)d_in[7];
    const float* W2 = (const float*)d_in[8];
    const float* b2 = (const float*)d_in[9];
    float* out = (float*)d_out;

    cudaFuncSetAttribute(gemm_qrnn, cudaFuncAttributeMaxDynamicSharedMemorySize, SMEM_BYTES);

    prepA<<<MTOT, 256>>>(x);
    prepB<<<dim3(2048 / 32, KK / 32), dim3(32, 8)>>>(W, V);
    gemm_qrnn<<<dim3(16, MTOT / 128), 256, SMEM_BYTES>>>(Vb);
    scan_combine<<<(B_ * NCH) / 256, 256>>>();
    q_head<<<NCH, 256>>>(W, V, Vb);
    mlp1<<<dim3(NCH / 128, B_), 128>>>(W0, b0);
    mlp2<<<dim3(NCH / 128, B_), 128>>>(W1, b1);
    mlp3<<<dim3(1, B_), 128>>>(W2, b2, out);
}

// round 11
// speedup vs baseline: 4.4445x; 2.3611x over previous
#include <cuda_runtime.h>
#include <cuda_fp16.h>
#include <cstdint>

// ---------------- problem constants ----------------
#define B_    32
#define S_    2048
#define DIN   512
#define NCH   1024
#define WLD   3072
#define MTOT  (B_*S_)       // 65536
#define KK    1024          // combined K = [x | xprev]
#define NCHUNK 16

// ---------------- scratch ----------------
__device__ __half g_Ah[(size_t)MTOT * KK];     // 128MB combined A (fp16)
__device__ __half g_Bh[2048 * KK];             // grouped/transposed f,z weights (fp16)
__device__ float2 g_part[NCHUNK * B_ * NCH];
__device__ float  g_c [B_ * NCH];
__device__ float  g_q0[B_ * NCH];
__device__ float  g_q1[B_ * NCH];

// ---------------- helpers ----------------
__device__ __forceinline__ float sigmoidf_(float x) {
    return __fdividef(1.0f, 1.0f + __expf(-x));
}
__device__ __forceinline__ float tanhf_(float x) {
    x = fminf(fmaxf(x, -15.0f), 15.0f);
    float e = __expf(-2.0f * x);
    return __fdividef(1.0f - e, 1.0f + e);
}
__device__ __forceinline__ uint32_t smem_u32(const void* p) {
    uint32_t a;
    asm("{ .reg .u64 t; cvta.to.shared.u64 t, %1; cvt.u32.u64 %0, t; }" : "=r"(a) : "l"(p));
    return a;
}

#define LDSM4(r0, r1, r2, r3, addr) \
    asm volatile("ldmatrix.sync.aligned.m8n8.x4.shared.b16 {%0,%1,%2,%3}, [%4];" \
        : "=r"(r0), "=r"(r1), "=r"(r2), "=r"(r3) : "r"(addr))

// ---------------- prep: combined A = [x | xprev] as fp16 ----------------
__global__ __launch_bounds__(256)
void prepA(const float* __restrict__ x) {
    int m = blockIdx.x;
    int q = threadIdx.x;                       // 4 floats per thread over 1024
    float4 v;
    if (q < 128) {
        v = reinterpret_cast<const float4*>(x)[(size_t)m * 128 + q];
    } else {
        if ((m & (S_ - 1)) == 0) v = make_float4(0.f, 0.f, 0.f, 0.f);
        else v = reinterpret_cast<const float4*>(x)[(size_t)(m - 1) * 128 + (q - 128)];
    }
    __half2* dst = reinterpret_cast<__half2*>(g_Ah) + (size_t)m * 512 + q * 2;
    dst[0] = __floats2half2_rn(v.x, v.y);
    dst[1] = __floats2half2_rn(v.z, v.w);
}

// ---------------- prep: Bh[n'][k]; n' groups of 128 = 64 f + 64 z channels ----------------
__global__ void prepB(const float* __restrict__ W, const float* __restrict__ V) {
    __shared__ float tile[32][33];
    int n0 = blockIdx.x * 32;
    int k0 = blockIdx.y * 32;
    int g  = n0 >> 7, rem = n0 & 127, fz = rem >> 6, c0 = rem & 63;
    int col0 = fz * NCH + g * 64 + c0;
    int tx = threadIdx.x, ty = threadIdx.y;   // block (32, 8)
#pragma unroll
    for (int i = 0; i < 4; i++) {
        int k = k0 + ty + i * 8;
        float v = (k < DIN) ? W[(size_t)k * WLD + col0 + tx]
                            : V[(size_t)(k - DIN) * WLD + col0 + tx];
        tile[ty + i * 8][tx] = v;
    }
    __syncthreads();
#pragma unroll
    for (int i = 0; i < 4; i++) {
        int nl = ty + i * 8;
        g_Bh[(size_t)(n0 + nl) * KK + k0 + tx] = __float2half_rn(tile[tx][nl]);
    }
}

// ---------------- main GEMM (fp16 m16n8k16) + fused activation + chunk scan ----------------
// CTA tile 128(M = one chunk of timesteps) x 128(N = 64 f + 64 z channels), BK=32, 3-stage.
// 8 warps, warp tile 64x32 (2m x 4n grid).
#define BK      32
#define PAD     40                      // halves per smem row (conflict-free)
#define TILE_H  (128*PAD)               // 5120 halves = 10240 B per A or B tile
#define STAGE_B (2*TILE_H*2)            // 20480 B per stage (A+B)
#define OFF_VB_B   67584                // after epilogue fz region (128*132*4)
#define OFF_SEG_B  68096
#define SMEM_BYTES 70144
#define FZ_STRIDE  132

__device__ __forceinline__ void stage_issue(uint32_t sbase, size_t m0, int n0,
                                            int t, int s) {
    const int kb = s * BK;
    const uint32_t base = sbase + (uint32_t)((s % 3) * STAGE_B);
#pragma unroll
    for (int j = 0; j < 2; j++) {
        int idx = t + j * 256;            // 0..511
        int r = idx >> 2, q = idx & 3;    // row, 16B-chunk
        uint32_t off = (uint32_t)(r * PAD + q * 8) * 2;
        const __half* ga = &g_Ah[(m0 + r) * KK + kb + q * 8];
        asm volatile("cp.async.ca.shared.global [%0], [%1], 16;"
                     :: "r"(base + off), "l"(ga));
        const __half* gb = &g_Bh[(size_t)(n0 + r) * KK + kb + q * 8];
        asm volatile("cp.async.ca.shared.global [%0], [%1], 16;"
                     :: "r"(base + 2 * TILE_H + off), "l"(gb));
    }
    asm volatile("cp.async.commit_group;");
}

__global__ __launch_bounds__(256, 2)
void gemm_qrnn(const float* __restrict__ Vb) {
    extern __shared__ float sm[];
    const uint32_t sbase = smem_u32(sm);
    const int t = threadIdx.x, lane = t & 31, w = t >> 5;
    const int bx = blockIdx.x, by = blockIdx.y;
    const size_t m0 = (size_t)by * 128;
    const int n0 = bx * 128;
    float* sVb = reinterpret_cast<float*>(reinterpret_cast<char*>(sm) + OFF_VB_B);

    if (t < 64)       sVb[t] = Vb[bx * 64 + t];
    else if (t < 128) sVb[t] = Vb[NCH + bx * 64 + (t - 64)];

    const int wm = (w >> 2) * 64, wn = (w & 3) * 32;
    const int rh = lane >> 2, cl = lane & 3;

    float acc[4][4][4];
#pragma unroll
    for (int mi = 0; mi < 4; mi++)
#pragma unroll
        for (int ni = 0; ni < 4; ni++)
#pragma unroll
            for (int j = 0; j < 4; j++) acc[mi][ni][j] = 0.0f;

    // precomputed ldmatrix lane addressing
    const uint32_t a_row = (uint32_t)(lane & 15);
    const uint32_t a_koff = (uint32_t)((lane >> 4) << 3);
    const uint32_t b_row = (uint32_t)(((lane >> 4) << 3) + (lane & 7));
    const uint32_t b_koff = (uint32_t)(((lane >> 3) & 1) << 3);

    stage_issue(sbase, m0, n0, t, 0);
    stage_issue(sbase, m0, n0, t, 1);

    for (int s = 0; s < KK / BK; s++) {
        if (s + 2 < KK / BK) stage_issue(sbase, m0, n0, t, s + 2);
        if (s < KK / BK - 2)       asm volatile("cp.async.wait_group 2;");
        else if (s == KK / BK - 2) asm volatile("cp.async.wait_group 1;");
        else                       asm volatile("cp.async.wait_group 0;");
        __syncthreads();

        const uint32_t Ab = sbase + (uint32_t)((s % 3) * STAGE_B);
        const uint32_t Bb = Ab + 2 * TILE_H;
#pragma unroll
        for (int k16 = 0; k16 < 2; k16++) {
            const uint32_t kb = k16 * 16;
            uint32_t a[4][4], b[4][2];
#pragma unroll
            for (int mi = 0; mi < 4; mi++) {
                uint32_t addr = Ab + ((wm + mi * 16 + a_row) * PAD + kb + a_koff) * 2;
                LDSM4(a[mi][0], a[mi][1], a[mi][2], a[mi][3], addr);
            }
#pragma unroll
            for (int nip = 0; nip < 2; nip++) {
                uint32_t addr = Bb + ((wn + nip * 16 + b_row) * PAD + kb + b_koff) * 2;
                LDSM4(b[2 * nip][0], b[2 * nip][1], b[2 * nip + 1][0], b[2 * nip + 1][1], addr);
            }
#pragma unroll
            for (int mi = 0; mi < 4; mi++)
#pragma unroll
                for (int ni = 0; ni < 4; ni++)
                    asm volatile(
                        "mma.sync.aligned.m16n8k16.row.col.f32.f16.f16.f32 "
                        "{%0,%1,%2,%3}, {%4,%5,%6,%7}, {%8,%9}, {%0,%1,%2,%3};"
                        : "+f"(acc[mi][ni][0]), "+f"(acc[mi][ni][1]),
                          "+f"(acc[mi][ni][2]), "+f"(acc[mi][ni][3])
                        : "r"(a[mi][0]), "r"(a[mi][1]), "r"(a[mi][2]), "r"(a[mi][3]),
                          "r"(b[ni][0]), "r"(b[ni][1]));
        }
        __syncthreads();
    }

    // ---- epilogue: raw pre -> smem tile [128 t][128 ch] (stride 132 floats) ----
    float* fz = sm;
#pragma unroll
    for (int mi = 0; mi < 4; mi++) {
        int row = wm + mi * 16 + rh;
#pragma unroll
        for (int ni = 0; ni < 4; ni++) {
            int col = wn + ni * 8 + cl * 2;
            *reinterpret_cast<float2*>(&fz[row * FZ_STRIDE + col]) =
                make_float2(acc[mi][ni][0], acc[mi][ni][1]);
            *reinterpret_cast<float2*>(&fz[(row + 8) * FZ_STRIDE + col]) =
                make_float2(acc[mi][ni][2], acc[mi][ni][3]);
        }
    }
    __syncthreads();

    // ---- activations + 4x32-step serial segment scan ----
    {
        const int ch = t & 63, seg = t >> 6;
        const float bf = sVb[ch], bz = sVb[64 + ch];
        float P = 1.0f, C = 0.0f;
#pragma unroll 4
        for (int i = 0; i < 32; i++) {
            int tt = seg * 32 + i;
            float pf = fz[tt * FZ_STRIDE + ch];
            float pz = fz[tt * FZ_STRIDE + 64 + ch];
            float f = sigmoidf_(pf + bf);
            float z = (1.0f - f) * tanhf_(pz + bz);
            C = fmaf(f, C, z);
            P *= f;
        }
        float2* segS = reinterpret_cast<float2*>(reinterpret_cast<char*>(sm) + OFF_SEG_B);
        segS[seg * 64 + ch] = make_float2(P, C);
    }
    __syncthreads();

    if (t < 64) {
        float2* segS = reinterpret_cast<float2*>(reinterpret_cast<char*>(sm) + OFF_SEG_B);
        float2 a0 = segS[t];
        float P = a0.x, C = a0.y;
#pragma unroll
        for (int sgi = 1; sgi < 4; sgi++) {
            float2 e = segS[sgi * 64 + t];
            C = fmaf(e.x, C, e.y);
            P *= e.x;
        }
        int b = by >> 4, chunk = by & 15;
        g_part[chunk * (B_ * NCH) + b * NCH + bx * 64 + t] = make_float2(P, C);
    }
}

// ---------------- serial combine over 16 chunks ----------------
__global__ __launch_bounds__(256)
void scan_combine() {
    int i = blockIdx.x * 256 + threadIdx.x;       // 32768
    float c = 0.0f;
#pragma unroll
    for (int ch = 0; ch < NCHUNK; ch++) {
        float2 pc = g_part[ch * (B_ * NCH) + i];
        c = fmaf(pc.x, c, pc.y);
    }
    g_c[i] = c;
}

// ---------------- head: weight-reuse GEMV; one CTA per channel ----------------
__global__ __launch_bounds__(256)
void q_head(const float* __restrict__ x, const float* __restrict__ W,
            const float* __restrict__ V, const float* __restrict__ Vb) {
    __shared__ float wcol[KK];
    int n = blockIdx.x;
    int t = threadIdx.x, lane = t & 31, wrp = t >> 5;
    for (int i = t; i < DIN; i += 256) {
        wcol[i]       = W[(size_t)i * WLD + 2 * NCH + n];
        wcol[DIN + i] = V[(size_t)i * WLD + 2 * NCH + n];
    }
    __syncthreads();
    float bias = Vb[2 * NCH + n];
#pragma unroll
    for (int bb = 0; bb < 4; bb++) {
        int b = wrp * 4 + bb;
        const float* xl = x + (size_t)(b * S_ + S_ - 1) * DIN;
        const float* xp = x + (size_t)(b * S_ + S_ - 2) * DIN;
        float acc = 0.0f;
#pragma unroll 4
        for (int kk = 0; kk < DIN / 32; kk++) {
            acc = fmaf(xl[kk * 32 + lane], wcol[kk * 32 + lane], acc);
            acc = fmaf(xp[kk * 32 + lane], wcol[DIN + kk * 32 + lane], acc);
        }
#pragma unroll
        for (int d = 16; d > 0; d >>= 1)
            acc += __shfl_down_sync(0xffffffffu, acc, d);
        if (lane == 0)
            g_q0[b * NCH + n] = g_c[b * NCH + n] * sigmoidf_(acc + bias);
    }
}

// ---------------- small MLP layers ----------------
__device__ __forceinline__ void mlp_body(const float* __restrict__ in,
                                         const float* __restrict__ Wt,
                                         const float* __restrict__ bias,
                                         float* __restrict__ out,
                                         float* s_in, int Kd, int Nd, bool relu) {
    int b = blockIdx.y, t = threadIdx.x;
    for (int i = t; i < Kd; i += 128) s_in[i] = in[b * Kd + i];
    __syncthreads();
    int n = blockIdx.x * 128 + t;
    float acc = bias[n];
#pragma unroll 8
    for (int k = 0; k < Kd; k++)
        acc = fmaf(s_in[k], Wt[(size_t)k * Nd + n], acc);
    if (relu) acc = fmaxf(acc, 0.0f);
    out[b * Nd + n] = acc;
}
__global__ __launch_bounds__(128) void mlp1(const float* __restrict__ W0, const float* __restrict__ b0)
{ __shared__ float s[NCH]; mlp_body(g_q0, W0, b0, g_q1, s, NCH, NCH, true); }
__global__ __launch_bounds__(128) void mlp2(const float* __restrict__ W1, const float* __restrict__ b1)
{ __shared__ float s[NCH]; mlp_body(g_q1, W1, b1, g_q0, s, NCH, NCH, true); }
__global__ __launch_bounds__(128) void mlp3(const float* __restrict__ W2, const float* __restrict__ b2,
                                            float* __restrict__ out)
{ __shared__ float s[NCH]; mlp_body(g_q0, W2, b2, out, s, NCH, 128, false); }

// ---------------- launcher ----------------
extern "C" void kernel_launch(void* const* d_in, const int* in_sizes, int n_in,
                              void* d_out, int out_size) {
    const float* x  = (const float*)d_in[0];
    const float* W  = (const float*)d_in[1];
    const float* V  = (const float*)d_in[2];
    const float* Vb = (const float*)d_in[3];
    const float* W0 = (const float*)d_in[4];
    const float* b0 = (const float*)d_in[5];
    const float* W1 = (const float*)d_in[6];
    const float* b1 = (const float*)d_in[7];
    const float* W2 = (const float*)d_in[8];
    const float* b2 = (const float*)d_in[9];
    float* out = (float*)d_out;

    cudaFuncSetAttribute(gemm_qrnn, cudaFuncAttributeMaxDynamicSharedMemorySize, SMEM_BYTES);

    prepA<<<MTOT, 256>>>(x);
    prepB<<<dim3(2048 / 32, KK / 32), dim3(32, 8)>>>(W, V);
    gemm_qrnn<<<dim3(16, MTOT / 128), 256, SMEM_BYTES>>>(Vb);
    scan_combine<<<(B_ * NCH) / 256, 256>>>();
    q_head<<<NCH, 256>>>(x, W, V, Vb);
    mlp1<<<dim3(NCH / 128, B_), 128>>>(W0, b0);
    mlp2<<<dim3(NCH / 128, B_), 128>>>(W1, b1);
    mlp3<<<dim3(1, B_), 128>>>(W2, b2, out);
}

// round 12
// speedup vs baseline: 4.7921x; 1.0782x over previous
#include <cuda_runtime.h>
#include <cuda_fp16.h>
#include <cstdint>

// ---------------- problem constants ----------------
#define B_    32
#define S_    2048
#define DIN   512
#define NCH   1024
#define WLD   3072
#define MTOT  (B_*S_)       // 65536
#define KK    1024          // combined K = [x | xprev]
#define NCHUNK 16

// ---------------- scratch ----------------
__device__ __half g_Ah[(size_t)MTOT * KK];     // 128MB combined A (fp16)
__device__ __half g_Bh[2048 * KK];             // grouped/transposed f,z weights (fp16)
__device__ float2 g_part[NCHUNK * B_ * NCH];
__device__ float  g_c [B_ * NCH];
__device__ float  g_q0[B_ * NCH];
__device__ float  g_q1[B_ * NCH];

// ---------------- helpers ----------------
__device__ __forceinline__ float sigmoidf_(float x) {
    return __fdividef(1.0f, 1.0f + __expf(-x));
}
__device__ __forceinline__ float tanhf_(float x) {
    x = fminf(fmaxf(x, -15.0f), 15.0f);
    float e = __expf(-2.0f * x);
    return __fdividef(1.0f - e, 1.0f + e);
}
__device__ __forceinline__ uint32_t smem_u32(const void* p) {
    uint32_t a;
    asm("{ .reg .u64 t; cvta.to.shared.u64 t, %1; cvt.u32.u64 %0, t; }" : "=r"(a) : "l"(p));
    return a;
}

#define LDSM4(r0, r1, r2, r3, addr) \
    asm volatile("ldmatrix.sync.aligned.m8n8.x4.shared.b16 {%0,%1,%2,%3}, [%4];" \
        : "=r"(r0), "=r"(r1), "=r"(r2), "=r"(r3) : "r"(addr))

// ---------------- prep: combined A = [x | xprev] as fp16 ----------------
__global__ __launch_bounds__(256)
void prepA(const float* __restrict__ x) {
    int m = blockIdx.x;
    int q = threadIdx.x;                       // 4 floats per thread over 1024
    float4 v;
    if (q < 128) {
        v = reinterpret_cast<const float4*>(x)[(size_t)m * 128 + q];
    } else {
        if ((m & (S_ - 1)) == 0) v = make_float4(0.f, 0.f, 0.f, 0.f);
        else v = reinterpret_cast<const float4*>(x)[(size_t)(m - 1) * 128 + (q - 128)];
    }
    __half2* dst = reinterpret_cast<__half2*>(g_Ah) + (size_t)m * 512 + q * 2;
    dst[0] = __floats2half2_rn(v.x, v.y);
    dst[1] = __floats2half2_rn(v.z, v.w);
}

// ---------------- prep: Bh[n'][k]; n' groups of 128 = 64 f + 64 z channels ----------------
__global__ void prepB(const float* __restrict__ W, const float* __restrict__ V) {
    __shared__ float tile[32][33];
    int n0 = blockIdx.x * 32;
    int k0 = blockIdx.y * 32;
    int g  = n0 >> 7, rem = n0 & 127, fz = rem >> 6, c0 = rem & 63;
    int col0 = fz * NCH + g * 64 + c0;
    int tx = threadIdx.x, ty = threadIdx.y;   // block (32, 8)
#pragma unroll
    for (int i = 0; i < 4; i++) {
        int k = k0 + ty + i * 8;
        float v = (k < DIN) ? W[(size_t)k * WLD + col0 + tx]
                            : V[(size_t)(k - DIN) * WLD + col0 + tx];
        tile[ty + i * 8][tx] = v;
    }
    __syncthreads();
#pragma unroll
    for (int i = 0; i < 4; i++) {
        int nl = ty + i * 8;
        g_Bh[(size_t)(n0 + nl) * KK + k0 + tx] = __float2half_rn(tile[tx][nl]);
    }
}

// ---------------- main GEMM (fp16 m16n8k16) + fused activation + chunk scan ----------------
// CTA tile 128(M = one chunk) x 256(N = 128 f + 128 z channels), BK=64, 3-stage, 512 thr.
// 16 warps, warp tile 64x32 (2m x 8n grid).
#define BKH     64
#define PADH    72                       // halves per smem row (ldmatrix conflict-free)
#define A_TILE_H (128*PADH)              // 9216 halves  = 18432 B
#define B_TILE_H (256*PADH)              // 18432 halves = 36864 B
#define STAGE_BYTES ((A_TILE_H + B_TILE_H)*2)   // 55296 B
#define OFF_VB_B   165888                // 3*STAGE_BYTES
#define OFF_SEG_B  166912
#define SMEM_BYTES 171008
#define FZ_STRIDE  260

__device__ __forceinline__ void stage_issue(uint32_t sbase, size_t m0, int n0,
                                            int t, int s) {
    const int kb = s * BKH;
    const uint32_t base = sbase + (uint32_t)((s % 3) * STAGE_BYTES);
    // A: 128 rows x 8 16B-chunks = 1024 loads (j = 0..1)
#pragma unroll
    for (int j = 0; j < 2; j++) {
        int idx = t + j * 512;
        int r = idx >> 3, q = idx & 7;
        uint32_t dst = base + (uint32_t)(r * PADH + q * 8) * 2;
        const __half* src = &g_Ah[(m0 + r) * KK + kb + q * 8];
        asm volatile("cp.async.cg.shared.global [%0], [%1], 16;" :: "r"(dst), "l"(src));
    }
    // B: 256 rows x 8 chunks = 2048 loads (j = 0..3)
#pragma unroll
    for (int j = 0; j < 4; j++) {
        int idx = t + j * 512;
        int r = idx >> 3, q = idx & 7;
        uint32_t dst = base + A_TILE_H * 2 + (uint32_t)(r * PADH + q * 8) * 2;
        const __half* src = &g_Bh[(size_t)(n0 + r) * KK + kb + q * 8];
        asm volatile("cp.async.cg.shared.global [%0], [%1], 16;" :: "r"(dst), "l"(src));
    }
    asm volatile("cp.async.commit_group;");
}

__global__ __launch_bounds__(512, 1)
void gemm_qrnn(const float* __restrict__ Vb) {
    extern __shared__ float sm[];
    const uint32_t sbase = smem_u32(sm);
    const int t = threadIdx.x, lane = t & 31, w = t >> 5;
    const int bx = blockIdx.x, by = blockIdx.y;
    const size_t m0 = (size_t)by * 128;
    const int n0 = bx * 256;
    float* sVb = reinterpret_cast<float*>(reinterpret_cast<char*>(sm) + OFF_VB_B);

    if (t < 128)      sVb[t] = Vb[bx * 128 + t];
    else if (t < 256) sVb[t] = Vb[NCH + bx * 128 + (t - 128)];

    const int wm = (w >> 3) * 64, wn = (w & 7) * 32;
    const int rh = lane >> 2, cl = lane & 3;

    float acc[4][4][4];
#pragma unroll
    for (int mi = 0; mi < 4; mi++)
#pragma unroll
        for (int ni = 0; ni < 4; ni++)
#pragma unroll
            for (int j = 0; j < 4; j++) acc[mi][ni][j] = 0.0f;

    // ldmatrix lane addressing
    const uint32_t a_row = (uint32_t)(lane & 15);
    const uint32_t a_koff = (uint32_t)((lane >> 4) << 3);
    const uint32_t b_row = (uint32_t)(((lane >> 4) << 3) + (lane & 7));
    const uint32_t b_koff = (uint32_t)(((lane >> 3) & 1) << 3);

    stage_issue(sbase, m0, n0, t, 0);
    stage_issue(sbase, m0, n0, t, 1);

    const int NS = KK / BKH;             // 16 stages
    for (int s = 0; s < NS; s++) {
        if (s + 2 < NS) stage_issue(sbase, m0, n0, t, s + 2);
        if (s < NS - 2)       asm volatile("cp.async.wait_group 2;");
        else if (s == NS - 2) asm volatile("cp.async.wait_group 1;");
        else                  asm volatile("cp.async.wait_group 0;");
        __syncthreads();

        const uint32_t Ab = sbase + (uint32_t)((s % 3) * STAGE_BYTES);
        const uint32_t Bb = Ab + A_TILE_H * 2;
#pragma unroll
        for (int k16 = 0; k16 < 4; k16++) {
            const uint32_t kb = k16 * 16;
            uint32_t a[4][4], b[4][2];
#pragma unroll
            for (int mi = 0; mi < 4; mi++) {
                uint32_t addr = Ab + ((wm + mi * 16 + a_row) * PADH + kb + a_koff) * 2;
                LDSM4(a[mi][0], a[mi][1], a[mi][2], a[mi][3], addr);
            }
#pragma unroll
            for (int nip = 0; nip < 2; nip++) {
                uint32_t addr = Bb + ((wn + nip * 16 + b_row) * PADH + kb + b_koff) * 2;
                LDSM4(b[2 * nip][0], b[2 * nip][1], b[2 * nip + 1][0], b[2 * nip + 1][1], addr);
            }
#pragma unroll
            for (int mi = 0; mi < 4; mi++)
#pragma unroll
                for (int ni = 0; ni < 4; ni++)
                    asm volatile(
                        "mma.sync.aligned.m16n8k16.row.col.f32.f16.f16.f32 "
                        "{%0,%1,%2,%3}, {%4,%5,%6,%7}, {%8,%9}, {%0,%1,%2,%3};"
                        : "+f"(acc[mi][ni][0]), "+f"(acc[mi][ni][1]),
                          "+f"(acc[mi][ni][2]), "+f"(acc[mi][ni][3])
                        : "r"(a[mi][0]), "r"(a[mi][1]), "r"(a[mi][2]), "r"(a[mi][3]),
                          "r"(b[ni][0]), "r"(b[ni][1]));
        }
        __syncthreads();
    }

    // ---- epilogue: raw pre -> smem tile [128 t][256 ch] (stride 260 floats) ----
    float* fz = sm;
#pragma unroll
    for (int mi = 0; mi < 4; mi++) {
        int row = wm + mi * 16 + rh;
#pragma unroll
        for (int ni = 0; ni < 4; ni++) {
            int col = wn + ni * 8 + cl * 2;
            *reinterpret_cast<float2*>(&fz[row * FZ_STRIDE + col]) =
                make_float2(acc[mi][ni][0], acc[mi][ni][1]);
            *reinterpret_cast<float2*>(&fz[(row + 8) * FZ_STRIDE + col]) =
                make_float2(acc[mi][ni][2], acc[mi][ni][3]);
        }
    }
    __syncthreads();

    // ---- activations + 4x32-step serial segment scan (512 thr = 4 seg x 128 ch) ----
    {
        const int c = t & 127, seg = t >> 7;
        const int fcol = (c >> 6) * 128 + (c & 63);
        const int zcol = fcol + 64;
        const float bf = sVb[c], bz = sVb[128 + c];
        float P = 1.0f, C = 0.0f;
#pragma unroll 4
        for (int i = 0; i < 32; i++) {
            int tt = seg * 32 + i;
            float f = sigmoidf_(fz[tt * FZ_STRIDE + fcol] + bf);
            float z = (1.0f - f) * tanhf_(fz[tt * FZ_STRIDE + zcol] + bz);
            C = fmaf(f, C, z);
            P *= f;
        }
        float2* segS = reinterpret_cast<float2*>(reinterpret_cast<char*>(sm) + OFF_SEG_B);
        segS[seg * 128 + c] = make_float2(P, C);
    }
    __syncthreads();

    if (t < 128) {
        float2* segS = reinterpret_cast<float2*>(reinterpret_cast<char*>(sm) + OFF_SEG_B);
        float2 a0 = segS[t];
        float P = a0.x, C = a0.y;
#pragma unroll
        for (int sgi = 1; sgi < 4; sgi++) {
            float2 e = segS[sgi * 128 + t];
            C = fmaf(e.x, C, e.y);
            P *= e.x;
        }
        int b = by >> 4, chunk = by & 15;
        g_part[chunk * (B_ * NCH) + b * NCH + bx * 128 + t] = make_float2(P, C);
    }
}

// ---------------- serial combine over 16 chunks ----------------
__global__ __launch_bounds__(256)
void scan_combine() {
    int i = blockIdx.x * 256 + threadIdx.x;       // 32768
    float c = 0.0f;
#pragma unroll
    for (int ch = 0; ch < NCHUNK; ch++) {
        float2 pc = g_part[ch * (B_ * NCH) + i];
        c = fmaf(pc.x, c, pc.y);
    }
    g_c[i] = c;
}

// ---------------- head: weight-reuse GEMV; one CTA per channel ----------------
__global__ __launch_bounds__(256)
void q_head(const float* __restrict__ x, const float* __restrict__ W,
            const float* __restrict__ V, const float* __restrict__ Vb) {
    __shared__ float wcol[KK];
    int n = blockIdx.x;
    int t = threadIdx.x, lane = t & 31, wrp = t >> 5;
    for (int i = t; i < DIN; i += 256) {
        wcol[i]       = W[(size_t)i * WLD + 2 * NCH + n];
        wcol[DIN + i] = V[(size_t)i * WLD + 2 * NCH + n];
    }
    __syncthreads();
    float bias = Vb[2 * NCH + n];
#pragma unroll
    for (int bb = 0; bb < 4; bb++) {
        int b = wrp * 4 + bb;
        const float* xl = x + (size_t)(b * S_ + S_ - 1) * DIN;
        const float* xp = x + (size_t)(b * S_ + S_ - 2) * DIN;
        float acc = 0.0f;
#pragma unroll 4
        for (int kk = 0; kk < DIN / 32; kk++) {
            acc = fmaf(xl[kk * 32 + lane], wcol[kk * 32 + lane], acc);
            acc = fmaf(xp[kk * 32 + lane], wcol[DIN + kk * 32 + lane], acc);
        }
#pragma unroll
        for (int d = 16; d > 0; d >>= 1)
            acc += __shfl_down_sync(0xffffffffu, acc, d);
        if (lane == 0)
            g_q0[b * NCH + n] = g_c[b * NCH + n] * sigmoidf_(acc + bias);
    }
}

// ---------------- small MLP layers ----------------
__device__ __forceinline__ void mlp_body(const float* __restrict__ in,
                                         const float* __restrict__ Wt,
                                         const float* __restrict__ bias,
                                         float* __restrict__ out,
                                         float* s_in, int Kd, int Nd, bool relu) {
    int b = blockIdx.y, t = threadIdx.x;
    for (int i = t; i < Kd; i += 128) s_in[i] = in[b * Kd + i];
    __syncthreads();
    int n = blockIdx.x * 128 + t;
    float acc = bias[n];
#pragma unroll 8
    for (int k = 0; k < Kd; k++)
        acc = fmaf(s_in[k], Wt[(size_t)k * Nd + n], acc);
    if (relu) acc = fmaxf(acc, 0.0f);
    out[b * Nd + n] = acc;
}
__global__ __launch_bounds__(128) void mlp1(const float* __restrict__ W0, const float* __restrict__ b0)
{ __shared__ float s[NCH]; mlp_body(g_q0, W0, b0, g_q1, s, NCH, NCH, true); }
__global__ __launch_bounds__(128) void mlp2(const float* __restrict__ W1, const float* __restrict__ b1)
{ __shared__ float s[NCH]; mlp_body(g_q1, W1, b1, g_q0, s, NCH, NCH, true); }
__global__ __launch_bounds__(128) void mlp3(const float* __restrict__ W2, const float* __restrict__ b2,
                                            float* __restrict__ out)
{ __shared__ float s[NCH]; mlp_body(g_q0, W2, b2, out, s, NCH, 128, false); }

// ---------------- launcher ----------------
extern "C" void kernel_launch(void* const* d_in, const int* in_sizes, int n_in,
                              void* d_out, int out_size) {
    const float* x  = (const float*)d_in[0];
    const float* W  = (const float*)d_in[1];
    const float* V  = (const float*)d_in[2];
    const float* Vb = (const float*)d_in[3];
    const float* W0 = (const float*)d_in[4];
    const float* b0 = (const float*)d_in[5];
    const float* W1 = (const float*)d_in[6];
    const float* b1 = (const float*)d_in[7];
    const float* W2 = (const float*)d_in[8];
    const float* b2 = (const float*)d_in[9];
    float* out = (float*)d_out;

    cudaFuncSetAttribute(gemm_qrnn, cudaFuncAttributeMaxDynamicSharedMemorySize, SMEM_BYTES);

    prepA<<<MTOT, 256>>>(x);
    prepB<<<dim3(2048 / 32, KK / 32), dim3(32, 8)>>>(W, V);
    gemm_qrnn<<<dim3(8, MTOT / 128), 512, SMEM_BYTES>>>(Vb);
    scan_combine<<<(B_ * NCH) / 256, 256>>>();
    q_head<<<NCH, 256>>>(x, W, V, Vb);
    mlp1<<<dim3(NCH / 128, B_), 128>>>(W0, b0);
    mlp2<<<dim3(NCH / 128, B_), 128>>>(W1, b1);
    mlp3<<<dim3(1, B_), 128>>>(W2, b2, out);
}

// round 14
// speedup vs baseline: 4.9103x; 1.0247x over previous
#include <cuda_runtime.h>
#include <cuda_fp16.h>
#include <cstdint>

// ---------------- problem constants ----------------
#define B_    32
#define S_    2048
#define DIN   512
#define NCH   1024
#define WLD   3072
#define MTOT  (B_*S_)       // 65536
#define KK    1024          // combined K = [x | xprev] (virtual; only x stored)
#define NCHUNK 16

// ---------------- scratch ----------------
__device__ __half g_xh[(size_t)MTOT * DIN];    // 64MB x in fp16 (L2-resident)
__device__ __half g_Bh[2048 * KK];             // grouped/transposed f,z weights (fp16)
__device__ float2 g_part[NCHUNK * B_ * NCH];
__device__ float  g_c [B_ * NCH];
__device__ float  g_q0[B_ * NCH];
__device__ float  g_q1[B_ * NCH];

// ---------------- helpers ----------------
__device__ __forceinline__ float sigmoidf_(float x) {
    return __fdividef(1.0f, 1.0f + __expf(-x));
}
__device__ __forceinline__ float tanhf_(float x) {
    x = fminf(fmaxf(x, -15.0f), 15.0f);
    float e = __expf(-2.0f * x);
    return __fdividef(1.0f - e, 1.0f + e);
}
__device__ __forceinline__ uint32_t smem_u32(const void* p) {
    uint32_t a;
    asm("{ .reg .u64 t; cvta.to.shared.u64 t, %1; cvt.u32.u64 %0, t; }" : "=r"(a) : "l"(p));
    return a;
}

#define LDSM4(r0, r1, r2, r3, addr) \
    asm volatile("ldmatrix.sync.aligned.m8n8.x4.shared.b16 {%0,%1,%2,%3}, [%4];" \
        : "=r"(r0), "=r"(r1), "=r"(r2), "=r"(r3) : "r"(addr))

// ---------------- prep: x -> fp16 ----------------
__global__ __launch_bounds__(128)
void prepA(const float* __restrict__ x) {
    int m = blockIdx.x;
    int q = threadIdx.x;                       // float4 index over 512-wide row
    float4 v = reinterpret_cast<const float4*>(x)[(size_t)m * 128 + q];
    __half2* dst = reinterpret_cast<__half2*>(g_xh) + (size_t)m * 256 + q * 2;
    dst[0] = __floats2half2_rn(v.x, v.y);
    dst[1] = __floats2half2_rn(v.z, v.w);
}

// ---------------- prep: Bh[n'][k]; n' groups of 128 = 64 f + 64 z channels ----------------
__global__ void prepB(const float* __restrict__ W, const float* __restrict__ V) {
    __shared__ float tile[32][33];
    int n0 = blockIdx.x * 32;
    int k0 = blockIdx.y * 32;
    int g  = n0 >> 7, rem = n0 & 127, fz = rem >> 6, c0 = rem & 63;
    int col0 = fz * NCH + g * 64 + c0;
    int tx = threadIdx.x, ty = threadIdx.y;   // block (32, 8)
#pragma unroll
    for (int i = 0; i < 4; i++) {
        int k = k0 + ty + i * 8;
        float v = (k < DIN) ? W[(size_t)k * WLD + col0 + tx]
                            : V[(size_t)(k - DIN) * WLD + col0 + tx];
        tile[ty + i * 8][tx] = v;
    }
    __syncthreads();
#pragma unroll
    for (int i = 0; i < 4; i++) {
        int nl = ty + i * 8;
        g_Bh[(size_t)(n0 + nl) * KK + k0 + tx] = __float2half_rn(tile[tx][nl]);
    }
}

// ---------------- main GEMM (fp16 m16n8k16) + fused activation + chunk scan ----------------
// CTA tile 128(M = one chunk) x 256(N = 128 f + 128 z), BK=64, 4-slot ring, 512 thr.
// Stages 0..7: k<512 -> x rows m0+r.  Stages 8..15: k>=512 -> x rows m0+r-1 (xprev),
// zero-filled for the sequence-start row via cp.async src-size 0.
#define BKH     64
#define PADH    72                       // halves per smem row (ldmatrix conflict-free)
#define A_TILE_H (128*PADH)              // 9216 halves  = 18432 B
#define B_TILE_H (256*PADH)              // 18432 halves = 36864 B
#define STAGE_BYTES ((A_TILE_H + B_TILE_H)*2)   // 55296 B
#define OFF_VB_B   221184                // 4*STAGE_BYTES
#define OFF_SEG_B  222208
#define SMEM_BYTES 226304
#define FZ_STRIDE  260

__device__ __forceinline__ void stage_issue(uint32_t sbase, size_t m0, int n0,
                                            int t, int s, int by) {
    const int kb = s * BKH;
    const uint32_t base = sbase + (uint32_t)((s & 3) * STAGE_BYTES);
    // A: 128 rows x 8 16B-chunks
#pragma unroll
    for (int j = 0; j < 2; j++) {
        int idx = t + j * 512;
        int r = idx >> 3, q = idx & 7;
        uint32_t dst = base + (uint32_t)(r * PADH + q * 8) * 2;
        const __half* src;
        uint32_t ssz = 16;
        if (kb < DIN) {
            src = &g_xh[(m0 + r) * DIN + kb + q * 8];
        } else {
            bool zr = (r == 0) && ((by & 15) == 0);   // sequence start: xprev = 0
            src = zr ? g_xh : &g_xh[(m0 + r - 1) * DIN + (kb - DIN) + q * 8];
            ssz = zr ? 0u : 16u;
        }
        asm volatile("cp.async.cg.shared.global [%0], [%1], 16, %2;"
                     :: "r"(dst), "l"(src), "r"(ssz));
    }
    // B: 256 rows x 8 chunks
#pragma unroll
    for (int j = 0; j < 4; j++) {
        int idx = t + j * 512;
        int r = idx >> 3, q = idx & 7;
        uint32_t dst = base + A_TILE_H * 2 + (uint32_t)(r * PADH + q * 8) * 2;
        const __half* src = &g_Bh[(size_t)(n0 + r) * KK + kb + q * 8];
        asm volatile("cp.async.cg.shared.global [%0], [%1], 16;" :: "r"(dst), "l"(src));
    }
    asm volatile("cp.async.commit_group;");
}

__global__ __launch_bounds__(512, 1)
void gemm_qrnn(const float* __restrict__ Vb) {
    extern __shared__ float sm[];
    const uint32_t sbase = smem_u32(sm);
    const int t = threadIdx.x, lane = t & 31, w = t >> 5;
    const int bx = blockIdx.x, by = blockIdx.y;
    const size_t m0 = (size_t)by * 128;
    const int n0 = bx * 256;
    float* sVb = reinterpret_cast<float*>(reinterpret_cast<char*>(sm) + OFF_VB_B);

    if (t < 128)      sVb[t] = Vb[bx * 128 + t];
    else if (t < 256) sVb[t] = Vb[NCH + bx * 128 + (t - 128)];

    const int wm = (w >> 3) * 64, wn = (w & 7) * 32;
    const int rh = lane >> 2, cl = lane & 3;

    float acc[4][4][4];
#pragma unroll
    for (int mi = 0; mi < 4; mi++)
#pragma unroll
        for (int ni = 0; ni < 4; ni++)
#pragma unroll
            for (int j = 0; j < 4; j++) acc[mi][ni][j] = 0.0f;

    // ldmatrix lane addressing
    const uint32_t a_row = (uint32_t)(lane & 15);
    const uint32_t a_koff = (uint32_t)((lane >> 4) << 3);
    const uint32_t b_row = (uint32_t)(((lane >> 4) << 3) + (lane & 7));
    const uint32_t b_koff = (uint32_t)(((lane >> 3) & 1) << 3);

    stage_issue(sbase, m0, n0, t, 0, by);
    stage_issue(sbase, m0, n0, t, 1, by);
    stage_issue(sbase, m0, n0, t, 2, by);

    const int NS = KK / BKH;             // 16 stages
    for (int s = 0; s < NS; s++) {
        // pending groups at this point: {s, s+1, s+2} (minus tail clipping)
        if (s < NS - 2)       asm volatile("cp.async.wait_group 2;");
        else if (s == NS - 2) asm volatile("cp.async.wait_group 1;");
        else                  asm volatile("cp.async.wait_group 0;");
        __syncthreads();     // all warps done reading slot (s-1)&3; stage s resident

        if (s + 3 < NS) stage_issue(sbase, m0, n0, t, s + 3, by);   // writes slot (s-1)&3

        const uint32_t Ab = sbase + (uint32_t)((s & 3) * STAGE_BYTES);
        const uint32_t Bb = Ab + A_TILE_H * 2;
#pragma unroll
        for (int k16 = 0; k16 < 4; k16++) {
            const uint32_t kb = k16 * 16;
            uint32_t a[4][4], b[4][2];
#pragma unroll
            for (int mi = 0; mi < 4; mi++) {
                uint32_t addr = Ab + ((wm + mi * 16 + a_row) * PADH + kb + a_koff) * 2;
                LDSM4(a[mi][0], a[mi][1], a[mi][2], a[mi][3], addr);
            }
#pragma unroll
            for (int nip = 0; nip < 2; nip++) {
                uint32_t addr = Bb + ((wn + nip * 16 + b_row) * PADH + kb + b_koff) * 2;
                LDSM4(b[2 * nip][0], b[2 * nip][1], b[2 * nip + 1][0], b[2 * nip + 1][1], addr);
            }
#pragma unroll
            for (int mi = 0; mi < 4; mi++)
#pragma unroll
                for (int ni = 0; ni < 4; ni++)
                    asm volatile(
                        "mma.sync.aligned.m16n8k16.row.col.f32.f16.f16.f32 "
                        "{%0,%1,%2,%3}, {%4,%5,%6,%7}, {%8,%9}, {%0,%1,%2,%3};"
                        : "+f"(acc[mi][ni][0]), "+f"(acc[mi][ni][1]),
                          "+f"(acc[mi][ni][2]), "+f"(acc[mi][ni][3])
                        : "r"(a[mi][0]), "r"(a[mi][1]), "r"(a[mi][2]), "r"(a[mi][3]),
                          "r"(b[ni][0]), "r"(b[ni][1]));
        }
    }
    __syncthreads();

    // ---- epilogue: raw pre -> smem tile [128 t][256 ch] (stride 260 floats) ----
    float* fz = sm;
#pragma unroll
    for (int mi = 0; mi < 4; mi++) {
        int row = wm + mi * 16 + rh;
#pragma unroll
        for (int ni = 0; ni < 4; ni++) {
            int col = wn + ni * 8 + cl * 2;
            *reinterpret_cast<float2*>(&fz[row * FZ_STRIDE + col]) =
                make_float2(acc[mi][ni][0], acc[mi][ni][1]);
            *reinterpret_cast<float2*>(&fz[(row + 8) * FZ_STRIDE + col]) =
                make_float2(acc[mi][ni][2], acc[mi][ni][3]);
        }
    }
    __syncthreads();

    // ---- activations + 4x32-step serial segment scan (512 thr = 4 seg x 128 ch) ----
    {
        const int c = t & 127, seg = t >> 7;
        const int fcol = (c >> 6) * 128 + (c & 63);
        const int zcol = fcol + 64;
        const float bf = sVb[c], bz = sVb[128 + c];
        float P = 1.0f, C = 0.0f;
#pragma unroll 4
        for (int i = 0; i < 32; i++) {
            int tt = seg * 32 + i;
            float f = sigmoidf_(fz[tt * FZ_STRIDE + fcol] + bf);
            float z = (1.0f - f) * tanhf_(fz[tt * FZ_STRIDE + zcol] + bz);
            C = fmaf(f, C, z);
            P *= f;
        }
        float2* segS = reinterpret_cast<float2*>(reinterpret_cast<char*>(sm) + OFF_SEG_B);
        segS[seg * 128 + c] = make_float2(P, C);
    }
    __syncthreads();

    if (t < 128) {
        float2* segS = reinterpret_cast<float2*>(reinterpret_cast<char*>(sm) + OFF_SEG_B);
        float2 a0 = segS[t];
        float P = a0.x, C = a0.y;
#pragma unroll
        for (int sgi = 1; sgi < 4; sgi++) {
            float2 e = segS[sgi * 128 + t];
            C = fmaf(e.x, C, e.y);
            P *= e.x;
        }
        int b = by >> 4, chunk = by & 15;
        g_part[chunk * (B_ * NCH) + b * NCH + bx * 128 + t] = make_float2(P, C);
    }
}

// ---------------- serial combine over 16 chunks ----------------
__global__ __launch_bounds__(256)
void scan_combine() {
    int i = blockIdx.x * 256 + threadIdx.x;       // 32768
    float c = 0.0f;
#pragma unroll
    for (int ch = 0; ch < NCHUNK; ch++) {
        float2 pc = g_part[ch * (B_ * NCH) + i];
        c = fmaf(pc.x, c, pc.y);
    }
    g_c[i] = c;
}

// ---------------- head: weight-reuse GEMV; one CTA per channel ----------------
__global__ __launch_bounds__(256)
void q_head(const float* __restrict__ x, const float* __restrict__ W,
            const float* __restrict__ V, const float* __restrict__ Vb) {
    __shared__ float wcol[KK];
    int n = blockIdx.x;
    int t = threadIdx.x, lane = t & 31, wrp = t >> 5;
    for (int i = t; i < DIN; i += 256) {
        wcol[i]       = W[(size_t)i * WLD + 2 * NCH + n];
        wcol[DIN + i] = V[(size_t)i * WLD + 2 * NCH + n];
    }
    __syncthreads();
    float bias = Vb[2 * NCH + n];
#pragma unroll
    for (int bb = 0; bb < 4; bb++) {
        int b = wrp * 4 + bb;
        const float* xl = x + (size_t)(b * S_ + S_ - 1) * DIN;
        const float* xp = x + (size_t)(b * S_ + S_ - 2) * DIN;
        float acc = 0.0f;
#pragma unroll 4
        for (int kk = 0; kk < DIN / 32; kk++) {
            acc = fmaf(xl[kk * 32 + lane], wcol[kk * 32 + lane], acc);
            acc = fmaf(xp[kk * 32 + lane], wcol[DIN + kk * 32 + lane], acc);
        }
#pragma unroll
        for (int d = 16; d > 0; d >>= 1)
            acc += __shfl_down_sync(0xffffffffu, acc, d);
        if (lane == 0)
            g_q0[b * NCH + n] = g_c[b * NCH + n] * sigmoidf_(acc + bias);
    }
}

// ---------------- small MLP layers ----------------
__device__ __forceinline__ void mlp_body(const float* __restrict__ in,
                                         const float* __restrict__ Wt,
                                         const float* __restrict__ bias,
                                         float* __restrict__ out,
                                         float* s_in, int Kd, int Nd, bool relu) {
    int b = blockIdx.y, t = threadIdx.x;
    for (int i = t; i < Kd; i += 128) s_in[i] = in[b * Kd + i];
    __syncthreads();
    int n = blockIdx.x * 128 + t;
    float acc = bias[n];
#pragma unroll 8
    for (int k = 0; k < Kd; k++)
        acc = fmaf(s_in[k], Wt[(size_t)k * Nd + n], acc);
    if (relu) acc = fmaxf(acc, 0.0f);
    out[b * Nd + n] = acc;
}
__global__ __launch_bounds__(128) void mlp1(const float* __restrict__ W0, const float* __restrict__ b0)
{ __shared__ float s[NCH]; mlp_body(g_q0, W0, b0, g_q1, s, NCH, NCH, true); }
__global__ __launch_bounds__(128) void mlp2(const float* __restrict__ W1, const float* __restrict__ b1)
{ __shared__ float s[NCH]; mlp_body(g_q1, W1, b1, g_q0, s, NCH, NCH, true); }
__global__ __launch_bounds__(128) void mlp3(const float* __restrict__ W2, const float* __restrict__ b2,
                                            float* __restrict__ out)
{ __shared__ float s[NCH]; mlp_body(g_q0, W2, b2, out, s, NCH, 128, false); }

// ---------------- launcher ----------------
extern "C" void kernel_launch(void* const* d_in, const int* in_sizes, int n_in,
                              void* d_out, int out_size) {
    const float* x  = (const float*)d_in[0];
    const float* W  = (const float*)d_in[1];
    const float* V  = (const float*)d_in[2];
    const float* Vb = (const float*)d_in[3];
    const float* W0 = (const float*)d_in[4];
    const float* b0 = (const float*)d_in[5];
    const float* W1 = (const float*)d_in[6];
    const float* b1 = (const float*)d_in[7];
    const float* W2 = (const float*)d_in[8];
    const float* b2 = (const float*)d_in[9];
    float* out = (float*)d_out;

    cudaFuncSetAttribute(gemm_qrnn, cudaFuncAttributeMaxDynamicSharedMemorySize, SMEM_BYTES);

    prepA<<<MTOT, 128>>>(x);
    prepB<<<dim3(2048 / 32, KK / 32), dim3(32, 8)>>>(W, V);
    gemm_qrnn<<<dim3(8, MTOT / 128), 512, SMEM_BYTES>>>(Vb);
    scan_combine<<<(B_ * NCH) / 256, 256>>>();
    q_head<<<NCH, 256>>>(x, W, V, Vb);
    mlp1<<<dim3(NCH / 128, B_), 128>>>(W0, b0);
    mlp2<<<dim3(NCH / 128, B_), 128>>>(W1, b1);
    mlp3<<<dim3(1, B_), 128>>>(W2, b2, out);
}